// round 3
// baseline (speedup 1.0000x reference)
#include <cuda_runtime.h>
#include <math_constants.h>

#define B_ 4
#define T_ 512
#define D_ 128
#define H_ 64
#define CS 64         // s-chunk for score phase
#define KP (H_ + 4)   // padded K row stride (68 -> conflict-free f4 lanes)

// Scratch: Q = input@Wt ; K' = input@Wx + demo@Wd + bh
__device__ float g_Q[B_*T_*H_];
__device__ float g_K[B_*T_*H_];

__device__ __forceinline__ float tanh_fast(float x) {
    float y;
    asm("tanh.approx.f32 %0, %1;" : "=f"(y) : "f"(x));
    return y;
}

// ---------------------------------------------------------------------------
// Kernel 1: per (b, 16-row tile) compute Q and K' rows.
// ---------------------------------------------------------------------------
__global__ __launch_bounds__(256) void prep_kernel(
    const float* __restrict__ input, const float* __restrict__ demo,
    const float* __restrict__ Wt, const float* __restrict__ Wx,
    const float* __restrict__ Wd, const float* __restrict__ bh)
{
    __shared__ float sx[16][D_];
    const int b  = blockIdx.y;
    const int t0 = blockIdx.x * 16;
    const int tid = threadIdx.x;

    {
        const float4* gin = (const float4*)(input + (size_t)(b*T_ + t0)*D_);
        float4* sx4 = (float4*)&sx[0][0];
        #pragma unroll
        for (int i = 0; i < 2; i++) sx4[tid + 256*i] = gin[tid + 256*i];
    }
    __syncthreads();

    const int h  = tid & 63;
    const int tg = tid >> 6;

    float dd = bh[h];
    #pragma unroll
    for (int j = 0; j < 12; j++) dd = fmaf(demo[b*12 + j], Wd[j*H_ + h], dd);

    float aq[4] = {0.f,0.f,0.f,0.f};
    float ak[4] = {0.f,0.f,0.f,0.f};
    #pragma unroll 4
    for (int d = 0; d < D_; d++) {
        float wt = Wt[d*H_ + h];
        float wx = Wx[d*H_ + h];
        #pragma unroll
        for (int i = 0; i < 4; i++) {
            float x = sx[tg + 4*i][d];
            aq[i] = fmaf(x, wt, aq[i]);
            ak[i] = fmaf(x, wx, ak[i]);
        }
    }
    #pragma unroll
    for (int i = 0; i < 4; i++) {
        int t = t0 + tg + 4*i;
        g_Q[(size_t)(b*T_ + t)*H_ + h] = aq[i];
        g_K[(size_t)(b*T_ + t)*H_ + h] = ak[i] + dd;
    }
}

// ---------------------------------------------------------------------------
// Kernel 2: scores + softmax(exp-before-mask) -> P written to out_e.
// 128 threads, 4 t-rows per CTA, grid (T/4, B) = 512 CTAs, 4 CTAs/SM.
// ---------------------------------------------------------------------------
__global__ __launch_bounds__(128, 4) void score_kernel(
    const float* __restrict__ Wa, const float* __restrict__ ba,
    float* __restrict__ out_e)
{
    __shared__ float sQ[4][H_];        // 1 KB
    __shared__ float sWa[H_];
    __shared__ float sK[CS][KP];       // 17.4 KB
    __shared__ float sSc[4][T_];       // 8 KB

    const int b   = blockIdx.y;
    const int t0  = blockIdx.x * 4;
    const int tid = threadIdx.x;

    {
        const float4* gq = (const float4*)(g_Q + (size_t)(b*T_ + t0)*H_);
        if (tid < 4*H_/4) ((float4*)sQ)[tid] = gq[tid];
        else if (tid < 64 + H_/4) ((float4*)sWa)[tid - 64] = ((const float4*)Wa)[tid - 64];
    }
    const float bav = ba[0];

    const int sl = tid & 63;   // s within chunk
    const int tg = tid >> 6;   // 0..1 -> rows tg and tg+2

    for (int c = 0; c < T_/CS; c++) {
        __syncthreads();
        {
            const float4* kp = (const float4*)(g_K + (size_t)(b*T_ + c*CS)*H_);
            const int j  = tid & 15;    // float4 within row
            const int r0 = tid >> 4;    // 8 rows per pass
            #pragma unroll
            for (int i = 0; i < 8; i++) {
                int r = r0 + 8*i;
                *(float4*)&sK[r][4*j] = kp[(size_t)r*16 + j];
            }
        }
        __syncthreads();

        float a0=0.f,a1=0.f,a2=0.f,a3=0.f,b0=0.f,b1=0.f,b2=0.f,b3=0.f;
        #pragma unroll
        for (int h4 = 0; h4 < H_/4; h4++) {
            float4 q0 = ((const float4*)sQ[tg])[h4];
            float4 q1 = ((const float4*)sQ[tg+2])[h4];
            float4 w  = ((const float4*)sWa)[h4];
            float4 k  = *(const float4*)&sK[sl][4*h4];
            a0 = fmaf(w.x, tanh_fast(q0.x + k.x), a0);
            a1 = fmaf(w.y, tanh_fast(q0.y + k.y), a1);
            a2 = fmaf(w.z, tanh_fast(q0.z + k.z), a2);
            a3 = fmaf(w.w, tanh_fast(q0.w + k.w), a3);
            b0 = fmaf(w.x, tanh_fast(q1.x + k.x), b0);
            b1 = fmaf(w.y, tanh_fast(q1.y + k.y), b1);
            b2 = fmaf(w.z, tanh_fast(q1.z + k.z), b2);
            b3 = fmaf(w.w, tanh_fast(q1.w + k.w), b3);
        }
        sSc[tg  ][c*CS + sl] = bav + ((a0 + a1) + (a2 + a3));
        sSc[tg+2][c*CS + sl] = bav + ((b0 + b1) + (b2 + b3));
    }
    __syncthreads();

    // softmax: warp w owns row w. max over FULL row, exp, THEN mask s<=t.
    {
        const int w    = tid >> 5;
        const int lane = tid & 31;
        const int t    = t0 + w;
        const float* row = sSc[w];
        float vals[T_/32];
        float m = -CUDART_INF_F;
        #pragma unroll
        for (int i = 0; i < T_/32; i++) {
            vals[i] = row[lane + 32*i];
            m = fmaxf(m, vals[i]);
        }
        #pragma unroll
        for (int off = 16; off; off >>= 1) m = fmaxf(m, __shfl_xor_sync(0xffffffffu, m, off));
        float sum = 0.f;
        #pragma unroll
        for (int i = 0; i < T_/32; i++) {
            int s = lane + 32*i;
            float e = __expf(vals[i] - m);
            if (s > t) e = 0.f;          // causal mask AFTER exp
            vals[i] = e;
            sum += e;
        }
        #pragma unroll
        for (int off = 16; off; off >>= 1) sum += __shfl_xor_sync(0xffffffffu, sum, off);
        float inv = 1.f / (sum + 1e-7f);
        float* ge = out_e + ((size_t)(b*T_ + t))*T_;
        #pragma unroll
        for (int i = 0; i < T_/32; i++) ge[lane + 32*i] = vals[i] * inv;
    }
}

// ---------------------------------------------------------------------------
// Kernel 3: v[b,t,:] = sum_s P[b,t,s] * input[b,s,:]. Warp per t-row.
// 256 threads, 8 rows/CTA, grid (T/8, B) = 256 CTAs. Low regs -> high occ.
// ---------------------------------------------------------------------------
__global__ __launch_bounds__(256) void v_kernel(
    const float* __restrict__ input, const float* __restrict__ P,
    float* __restrict__ out_v)
{
    __shared__ float sIn[32][D_];      // 16 KB input chunk
    const int b   = blockIdx.y;
    const int t0  = blockIdx.x * 8;
    const int tid = threadIdx.x;
    const int w   = tid >> 5;          // warp -> row
    const int d4  = tid & 31;          // float4 column

    const float* Pr = P + (size_t)(b*T_ + t0 + w)*T_;
    float4 acc = make_float4(0.f,0.f,0.f,0.f);

    for (int c = 0; c < T_/32; c++) {
        __syncthreads();
        {
            const float4* gin = (const float4*)(input + (size_t)(b*T_ + c*32)*D_);
            #pragma unroll
            for (int i = 0; i < 4; i++) ((float4*)sIn)[tid + 256*i] = gin[tid + 256*i];
        }
        __syncthreads();
        #pragma unroll
        for (int s4 = 0; s4 < 8; s4++) {
            float4 p4 = __ldg((const float4*)(Pr + c*32 + 4*s4));  // warp-uniform
            #pragma unroll
            for (int j = 0; j < 4; j++) {
                float p = (&p4.x)[j];
                float4 x = ((const float4*)sIn[4*s4 + j])[d4];
                acc.x = fmaf(p, x.x, acc.x);
                acc.y = fmaf(p, x.y, acc.y);
                acc.z = fmaf(p, x.z, acc.z);
                acc.w = fmaf(p, x.w, acc.w);
            }
        }
    }
    ((float4*)(out_v + (size_t)(b*T_ + t0 + w)*D_))[d4] = acc;
}

// ---------------------------------------------------------------------------
extern "C" void kernel_launch(void* const* d_in, const int* in_sizes, int n_in,
                              void* d_out, int out_size)
{
    const float* input = (const float*)d_in[0];
    const float* demo  = (const float*)d_in[1];
    const float* Wt    = (const float*)d_in[2];
    const float* Wx    = (const float*)d_in[3];
    const float* Wd    = (const float*)d_in[4];
    const float* bh    = (const float*)d_in[5];
    const float* Wa    = (const float*)d_in[6];
    const float* ba    = (const float*)d_in[7];

    float* out_v = (float*)d_out;                   // [B,T,D]
    float* out_e = out_v + (size_t)B_ * T_ * D_;    // [B,T,T]

    dim3 g1(T_/16, B_);
    prep_kernel<<<g1, 256>>>(input, demo, Wt, Wx, Wd, bh);

    dim3 g2(T_/4, B_);
    score_kernel<<<g2, 128>>>(Wa, ba, out_e);

    dim3 g3(T_/8, B_);
    v_kernel<<<g3, 256>>>(input, out_e, out_v);
}

// round 4
// speedup vs baseline: 1.1274x; 1.1274x over previous
#include <cuda_runtime.h>
#include <cuda_pipeline.h>
#include <math_constants.h>

#define B_ 4
#define T_ 512
#define D_ 128
#define H_ 64
#define CS 64         // s-chunk for score phase
#define KP (H_ + 4)   // padded K row stride (68 -> conflict-free f4 lanes)

// Scratch: Q = input@Wt ; K' = input@Wx + demo@Wd + bh
__device__ float g_Q[B_*T_*H_];
__device__ float g_K[B_*T_*H_];

__device__ __forceinline__ float tanh_fast(float x) {
    float y;
    asm("tanh.approx.f32 %0, %1;" : "=f"(y) : "f"(x));
    return y;
}

// ---------------------------------------------------------------------------
// Kernel 1: Q/K' prep. 8 t-rows per CTA, grid (T/8, B) = 256 CTAs.
// W staged through smem in two 32KB passes -> LDS+FFMA inner loop.
// ---------------------------------------------------------------------------
__global__ __launch_bounds__(256) void prep_kernel(
    const float* __restrict__ input, const float* __restrict__ demo,
    const float* __restrict__ Wt, const float* __restrict__ Wx,
    const float* __restrict__ Wd, const float* __restrict__ bh)
{
    __shared__ float sx[8][D_];        // 4 KB
    __shared__ float sWt[64][H_];      // 16 KB
    __shared__ float sWx[64][H_];      // 16 KB

    const int b   = blockIdx.y;
    const int t0  = blockIdx.x * 8;
    const int tid = threadIdx.x;
    const int h   = tid & 63;
    const int rg  = tid >> 6;          // 0..3 -> rows rg, rg+4

    // load 8 input rows (coalesced float4, one per thread)
    {
        const float4* gin = (const float4*)(input + (size_t)(b*T_ + t0)*D_);
        ((float4*)&sx[0][0])[tid] = gin[tid];
    }

    float dd = bh[h];
    #pragma unroll
    for (int j = 0; j < 12; j++) dd = fmaf(demo[b*12 + j], Wd[j*H_ + h], dd);

    float aq0=0.f, ak0=0.f, aq1=0.f, ak1=0.f;

    #pragma unroll
    for (int p = 0; p < 2; p++) {
        __syncthreads();
        {   // stage 64 rows of Wt and Wx (each 16KB), coalesced
            const float4* gt = (const float4*)(Wt + (size_t)(64*p)*H_);
            const float4* gx = (const float4*)(Wx + (size_t)(64*p)*H_);
            #pragma unroll
            for (int i = 0; i < 4; i++) {
                ((float4*)&sWt[0][0])[tid + 256*i] = gt[tid + 256*i];
                ((float4*)&sWx[0][0])[tid + 256*i] = gx[tid + 256*i];
            }
        }
        __syncthreads();

        #pragma unroll 8
        for (int d = 0; d < 64; d++) {
            float wt = sWt[d][h];
            float wx = sWx[d][h];
            float x0 = sx[rg    ][64*p + d];
            float x1 = sx[rg + 4][64*p + d];
            aq0 = fmaf(x0, wt, aq0);
            ak0 = fmaf(x0, wx, ak0);
            aq1 = fmaf(x1, wt, aq1);
            ak1 = fmaf(x1, wx, ak1);
        }
    }

    const size_t o0 = (size_t)(b*T_ + t0 + rg    )*H_ + h;
    const size_t o1 = (size_t)(b*T_ + t0 + rg + 4)*H_ + h;
    g_Q[o0] = aq0;  g_K[o0] = ak0 + dd;
    g_Q[o1] = aq1;  g_K[o1] = ak1 + dd;
}

// ---------------------------------------------------------------------------
// Kernel 2: scores + softmax(exp-before-mask) -> P written to out_e.
// 128 threads, 4 t-rows/CTA, grid (T/4, B) = 512 CTAs.
// K' chunks double-buffered via cp.async.
// ---------------------------------------------------------------------------
__global__ __launch_bounds__(128, 5) void score_kernel(
    const float* __restrict__ Wa, const float* __restrict__ ba,
    float* __restrict__ out_e)
{
    __shared__ float sQ[4][H_];        // 1 KB
    __shared__ float sWa[H_];
    __shared__ float sK[2][CS][KP];    // 34.8 KB double-buffered
    __shared__ float sSc[4][T_];       // 8 KB

    const int b   = blockIdx.y;
    const int t0  = blockIdx.x * 4;
    const int tid = threadIdx.x;

    {
        const float4* gq = (const float4*)(g_Q + (size_t)(b*T_ + t0)*H_);
        if (tid < 4*H_/4) ((float4*)sQ)[tid] = gq[tid];
        else if (tid < 64 + H_/4) ((float4*)sWa)[tid - 64] = ((const float4*)Wa)[tid - 64];
    }
    const float bav = ba[0];

    const int sl = tid & 63;   // s within chunk
    const int tg = tid >> 6;   // 0..1 -> rows tg and tg+2

    const float4* kbase = (const float4*)(g_K + (size_t)(b*T_)*H_);
    const int j  = tid & 15;   // float4 within K row
    const int r0 = tid >> 4;   // 8 rows per pass

    // prefetch chunk 0 into buf 0
    #pragma unroll
    for (int i = 0; i < 8; i++) {
        int r = r0 + 8*i;
        __pipeline_memcpy_async(&sK[0][r][4*j], &kbase[(size_t)r*16 + j], 16);
    }
    __pipeline_commit();

    const int NC = T_/CS;   // 8 chunks
    for (int c = 0; c < NC; c++) {
        if (c + 1 < NC) {
            const float4* kp = kbase + (size_t)(c+1)*CS*16;
            #pragma unroll
            for (int i = 0; i < 8; i++) {
                int r = r0 + 8*i;
                __pipeline_memcpy_async(&sK[(c+1)&1][r][4*j], &kp[(size_t)r*16 + j], 16);
            }
            __pipeline_commit();
            __pipeline_wait_prior(1);
        } else {
            __pipeline_wait_prior(0);
        }
        __syncthreads();   // chunk c visible to all; also covers initial sQ/sWa

        const float (*kb)[KP] = sK[c & 1];
        float a0=0.f,a1=0.f,a2=0.f,a3=0.f,b0=0.f,b1=0.f,b2=0.f,b3=0.f;
        #pragma unroll
        for (int h4 = 0; h4 < H_/4; h4++) {
            float4 q0 = ((const float4*)sQ[tg])[h4];
            float4 q1 = ((const float4*)sQ[tg+2])[h4];
            float4 w  = ((const float4*)sWa)[h4];
            float4 k  = *(const float4*)&kb[sl][4*h4];
            a0 = fmaf(w.x, tanh_fast(q0.x + k.x), a0);
            a1 = fmaf(w.y, tanh_fast(q0.y + k.y), a1);
            a2 = fmaf(w.z, tanh_fast(q0.z + k.z), a2);
            a3 = fmaf(w.w, tanh_fast(q0.w + k.w), a3);
            b0 = fmaf(w.x, tanh_fast(q1.x + k.x), b0);
            b1 = fmaf(w.y, tanh_fast(q1.y + k.y), b1);
            b2 = fmaf(w.z, tanh_fast(q1.z + k.z), b2);
            b3 = fmaf(w.w, tanh_fast(q1.w + k.w), b3);
        }
        sSc[tg  ][c*CS + sl] = bav + ((a0 + a1) + (a2 + a3));
        sSc[tg+2][c*CS + sl] = bav + ((b0 + b1) + (b2 + b3));
        __syncthreads();   // done reading buf (c&1) before prefetch of c+2 overwrites it
    }

    // softmax: warp w owns row w. max over FULL row, exp, THEN mask s<=t.
    {
        const int w    = tid >> 5;
        const int lane = tid & 31;
        const int t    = t0 + w;
        const float* row = sSc[w];
        float vals[T_/32];
        float m = -CUDART_INF_F;
        #pragma unroll
        for (int i = 0; i < T_/32; i++) {
            vals[i] = row[lane + 32*i];
            m = fmaxf(m, vals[i]);
        }
        #pragma unroll
        for (int off = 16; off; off >>= 1) m = fmaxf(m, __shfl_xor_sync(0xffffffffu, m, off));
        float sum = 0.f;
        #pragma unroll
        for (int i = 0; i < T_/32; i++) {
            int s = lane + 32*i;
            float e = __expf(vals[i] - m);
            if (s > t) e = 0.f;          // causal mask AFTER exp
            vals[i] = e;
            sum += e;
        }
        #pragma unroll
        for (int off = 16; off; off >>= 1) sum += __shfl_xor_sync(0xffffffffu, sum, off);
        float inv = 1.f / (sum + 1e-7f);
        float* ge = out_e + ((size_t)(b*T_ + t))*T_;
        #pragma unroll
        for (int i = 0; i < T_/32; i++) ge[lane + 32*i] = vals[i] * inv;
    }
}

// ---------------------------------------------------------------------------
// Kernel 3: v[b,t,:] = sum_s P[b,t,s] * input[b,s,:]. Warp per t-row.
// ---------------------------------------------------------------------------
__global__ __launch_bounds__(256) void v_kernel(
    const float* __restrict__ input, const float* __restrict__ P,
    float* __restrict__ out_v)
{
    __shared__ float sIn[32][D_];      // 16 KB input chunk
    const int b   = blockIdx.y;
    const int t0  = blockIdx.x * 8;
    const int tid = threadIdx.x;
    const int w   = tid >> 5;          // warp -> row
    const int d4  = tid & 31;          // float4 column

    const float* Pr = P + (size_t)(b*T_ + t0 + w)*T_;
    float4 acc = make_float4(0.f,0.f,0.f,0.f);

    for (int c = 0; c < T_/32; c++) {
        __syncthreads();
        {
            const float4* gin = (const float4*)(input + (size_t)(b*T_ + c*32)*D_);
            #pragma unroll
            for (int i = 0; i < 4; i++) ((float4*)sIn)[tid + 256*i] = gin[tid + 256*i];
        }
        __syncthreads();
        #pragma unroll
        for (int s4 = 0; s4 < 8; s4++) {
            float4 p4 = __ldg((const float4*)(Pr + c*32 + 4*s4));  // warp-uniform
            #pragma unroll
            for (int jj = 0; jj < 4; jj++) {
                float p = (&p4.x)[jj];
                float4 x = ((const float4*)sIn[4*s4 + jj])[d4];
                acc.x = fmaf(p, x.x, acc.x);
                acc.y = fmaf(p, x.y, acc.y);
                acc.z = fmaf(p, x.z, acc.z);
                acc.w = fmaf(p, x.w, acc.w);
            }
        }
    }
    ((float4*)(out_v + (size_t)(b*T_ + t0 + w)*D_))[d4] = acc;
}

// ---------------------------------------------------------------------------
extern "C" void kernel_launch(void* const* d_in, const int* in_sizes, int n_in,
                              void* d_out, int out_size)
{
    const float* input = (const float*)d_in[0];
    const float* demo  = (const float*)d_in[1];
    const float* Wt    = (const float*)d_in[2];
    const float* Wx    = (const float*)d_in[3];
    const float* Wd    = (const float*)d_in[4];
    const float* bh    = (const float*)d_in[5];
    const float* Wa    = (const float*)d_in[6];
    const float* ba    = (const float*)d_in[7];

    float* out_v = (float*)d_out;                   // [B,T,D]
    float* out_e = out_v + (size_t)B_ * T_ * D_;    // [B,T,T]

    dim3 g1(T_/8, B_);
    prep_kernel<<<g1, 256>>>(input, demo, Wt, Wx, Wd, bh);

    dim3 g2(T_/4, B_);
    score_kernel<<<g2, 128>>>(Wa, ba, out_e);

    dim3 g3(T_/8, B_);
    v_kernel<<<g3, 256>>>(input, out_e, out_v);
}

// round 5
// speedup vs baseline: 1.3413x; 1.1897x over previous
#include <cuda_runtime.h>
#include <cuda_pipeline.h>
#include <math_constants.h>

#define B_ 4
#define T_ 512
#define D_ 128
#define H_ 64
#define KP (H_ + 4)   // padded K row stride (68 -> conflict-free f4 lanes)

// Scratch: Q = input@Wt ; K' = input@Wx + demo@Wd + bh
__device__ float g_Q[B_*T_*H_];
__device__ float g_K[B_*T_*H_];

__device__ __forceinline__ float tanh_fast(float x) {
    float y;
    asm("tanh.approx.f32 %0, %1;" : "=f"(y) : "f"(x));
    return y;
}

// ---------------------------------------------------------------------------
// Kernel 1: Q/K' prep. 8 t-rows per CTA, grid (T/8, B) = 256 CTAs.
// W staged via cp.async double buffer, 4 passes of 32 rows.
// ---------------------------------------------------------------------------
__global__ __launch_bounds__(256) void prep_kernel(
    const float* __restrict__ input, const float* __restrict__ demo,
    const float* __restrict__ Wt, const float* __restrict__ Wx,
    const float* __restrict__ Wd, const float* __restrict__ bh)
{
    __shared__ float sx[8][D_];            // 4 KB
    __shared__ float sW[2][2][32][H_];     // 32 KB  [buf][t/x][row][h]

    const int b   = blockIdx.y;
    const int t0  = blockIdx.x * 8;
    const int tid = threadIdx.x;
    const int h   = tid & 63;
    const int rg  = tid >> 6;              // 0..3 -> rows rg, rg+4

    // 8 input rows, coalesced float4 (256 f4 total)
    {
        const float4* gin = (const float4*)(input + (size_t)(b*T_ + t0)*D_);
        ((float4*)&sx[0][0])[tid] = gin[tid];
    }

    // prefetch W pass 0
    {
        const float4* gt = (const float4*)(Wt);
        const float4* gx = (const float4*)(Wx);
        #pragma unroll
        for (int i = 0; i < 2; i++) {
            int idx = tid + 256*i;
            __pipeline_memcpy_async(&((float4*)sW[0][0])[idx], &gt[idx], 16);
            __pipeline_memcpy_async(&((float4*)sW[0][1])[idx], &gx[idx], 16);
        }
        __pipeline_commit();
    }

    float dd = bh[h];
    #pragma unroll
    for (int j = 0; j < 12; j++) dd = fmaf(demo[b*12 + j], Wd[j*H_ + h], dd);

    float aq0=0.f, ak0=0.f, aq1=0.f, ak1=0.f;

    #pragma unroll
    for (int p = 0; p < 4; p++) {
        if (p < 3) {
            const float4* gt = (const float4*)(Wt + (size_t)(32*(p+1))*H_);
            const float4* gx = (const float4*)(Wx + (size_t)(32*(p+1))*H_);
            const int buf = (p+1) & 1;
            #pragma unroll
            for (int i = 0; i < 2; i++) {
                int idx = tid + 256*i;
                __pipeline_memcpy_async(&((float4*)sW[buf][0])[idx], &gt[idx], 16);
                __pipeline_memcpy_async(&((float4*)sW[buf][1])[idx], &gx[idx], 16);
            }
            __pipeline_commit();
            __pipeline_wait_prior(1);
        } else {
            __pipeline_wait_prior(0);
        }
        __syncthreads();

        const int bp = p & 1;
        #pragma unroll 8
        for (int d = 0; d < 32; d++) {
            float wt = sW[bp][0][d][h];
            float wx = sW[bp][1][d][h];
            float x0 = sx[rg    ][32*p + d];
            float x1 = sx[rg + 4][32*p + d];
            aq0 = fmaf(x0, wt, aq0);
            ak0 = fmaf(x0, wx, ak0);
            aq1 = fmaf(x1, wt, aq1);
            ak1 = fmaf(x1, wx, ak1);
        }
        __syncthreads();   // all readers done before buf reuse
    }

    const size_t o0 = (size_t)(b*T_ + t0 + rg    )*H_ + h;
    const size_t o1 = (size_t)(b*T_ + t0 + rg + 4)*H_ + h;
    g_Q[o0] = aq0;  g_K[o0] = ak0 + dd;
    g_Q[o1] = aq1;  g_K[o1] = ak1 + dd;
}

// ---------------------------------------------------------------------------
// Kernel 2: RAW scores only. CTA = 8 t-rows x 128 s-cols, 128 threads.
// grid (T/8, T/128, B) = (64, 4, 4) = 1024 CTAs. One-shot K tile, one sync.
// e_raw[t][s] = ba + sum_h Wa[h]*tanh(Q[t][h] + K'[s][h])  -> out_e
// ---------------------------------------------------------------------------
__global__ __launch_bounds__(128, 6) void score_kernel(
    const float* __restrict__ Wa, const float* __restrict__ ba,
    float* __restrict__ out_e)
{
    __shared__ float sQ[8][H_];        // 2 KB
    __shared__ float sWa[H_];
    __shared__ float sK[128][KP];      // 34.8 KB

    const int b   = blockIdx.z;
    const int s0  = blockIdx.y * 128;
    const int t0  = blockIdx.x * 8;
    const int tid = threadIdx.x;

    // Q tile: 8 rows = 128 f4, one per thread
    {
        const float4* gq = (const float4*)(g_Q + (size_t)(b*T_ + t0)*H_);
        ((float4*)sQ)[tid] = gq[tid];
        if (tid < H_/4) ((float4*)sWa)[tid] = ((const float4*)Wa)[tid];
    }

    // K tile: 128 rows x 16 f4 via cp.async (16 per thread)
    {
        const float4* kp = (const float4*)(g_K + (size_t)(b*T_ + s0)*H_);
        const int j  = tid & 15;
        const int r0 = tid >> 4;
        #pragma unroll
        for (int i = 0; i < 16; i++) {
            int r = r0 + 8*i;
            __pipeline_memcpy_async(&sK[r][4*j], &kp[(size_t)r*16 + j], 16);
        }
        __pipeline_commit();
    }
    __pipeline_wait_prior(0);
    __syncthreads();

    const int s = tid;
    float acc[8] = {0.f,0.f,0.f,0.f,0.f,0.f,0.f,0.f};

    #pragma unroll
    for (int h4 = 0; h4 < H_/4; h4++) {
        float4 k = *(const float4*)&sK[s][4*h4];
        float4 w = ((const float4*)sWa)[h4];
        #pragma unroll
        for (int t = 0; t < 8; t++) {
            float4 q = ((const float4*)sQ[t])[h4];
            acc[t] = fmaf(w.x, tanh_fast(q.x + k.x), acc[t]);
            acc[t] = fmaf(w.y, tanh_fast(q.y + k.y), acc[t]);
            acc[t] = fmaf(w.z, tanh_fast(q.z + k.z), acc[t]);
            acc[t] = fmaf(w.w, tanh_fast(q.w + k.w), acc[t]);
        }
    }

    const float bav = ba[0];
    float* ge = out_e + ((size_t)(b*T_ + t0))*T_ + s0 + s;
    #pragma unroll
    for (int t = 0; t < 8; t++) ge[(size_t)t*T_] = acc[t] + bav;
}

// ---------------------------------------------------------------------------
// Kernel 3: fused softmax + v. Warp per t-row, 8 rows/CTA, 256 threads.
// Reads raw scores from out_e, writes normalized P back to out_e,
// then v[t,:] = sum_s P[t,s]*input[s,:] with input chunks staged in smem.
// ---------------------------------------------------------------------------
__global__ __launch_bounds__(256) void sv_kernel(
    const float* __restrict__ input, float* __restrict__ out_e,
    float* __restrict__ out_v)
{
    __shared__ float sP[8][T_];        // 16 KB
    __shared__ float sIn[32][D_];      // 16 KB

    const int b    = blockIdx.y;
    const int t0   = blockIdx.x * 8;
    const int tid  = threadIdx.x;
    const int w    = tid >> 5;
    const int lane = tid & 31;
    const int t    = t0 + w;

    // ---- softmax over raw row (max over FULL row, exp, THEN mask s<=t) ----
    {
        float* ge = out_e + ((size_t)(b*T_ + t))*T_;
        float vals[T_/32];
        float m = -CUDART_INF_F;
        #pragma unroll
        for (int i = 0; i < T_/32; i++) {
            vals[i] = ge[lane + 32*i];
            m = fmaxf(m, vals[i]);
        }
        #pragma unroll
        for (int off = 16; off; off >>= 1) m = fmaxf(m, __shfl_xor_sync(0xffffffffu, m, off));
        float sum = 0.f;
        #pragma unroll
        for (int i = 0; i < T_/32; i++) {
            int s = lane + 32*i;
            float e = __expf(vals[i] - m);
            if (s > t) e = 0.f;          // causal mask AFTER exp
            vals[i] = e;
            sum += e;
        }
        #pragma unroll
        for (int off = 16; off; off >>= 1) sum += __shfl_xor_sync(0xffffffffu, sum, off);
        float inv = 1.f / (sum + 1e-7f);
        #pragma unroll
        for (int i = 0; i < T_/32; i++) {
            int s = lane + 32*i;
            float p = vals[i] * inv;
            ge[s]    = p;
            sP[w][s] = p;
        }
        __syncwarp();
    }

    // ---- v phase ----
    float4 acc = make_float4(0.f,0.f,0.f,0.f);
    for (int c = 0; c < T_/32; c++) {
        __syncthreads();
        {
            const float4* gin = (const float4*)(input + (size_t)(b*T_ + c*32)*D_);
            #pragma unroll
            for (int i = 0; i < 4; i++) ((float4*)sIn)[tid + 256*i] = gin[tid + 256*i];
        }
        __syncthreads();
        #pragma unroll
        for (int s = 0; s < 32; s++) {
            float p = sP[w][c*32 + s];
            float4 x = ((const float4*)sIn[s])[lane];
            acc.x = fmaf(p, x.x, acc.x);
            acc.y = fmaf(p, x.y, acc.y);
            acc.z = fmaf(p, x.z, acc.z);
            acc.w = fmaf(p, x.w, acc.w);
        }
    }
    ((float4*)(out_v + (size_t)(b*T_ + t)*D_))[lane] = acc;
}

// ---------------------------------------------------------------------------
extern "C" void kernel_launch(void* const* d_in, const int* in_sizes, int n_in,
                              void* d_out, int out_size)
{
    const float* input = (const float*)d_in[0];
    const float* demo  = (const float*)d_in[1];
    const float* Wt    = (const float*)d_in[2];
    const float* Wx    = (const float*)d_in[3];
    const float* Wd    = (const float*)d_in[4];
    const float* bh    = (const float*)d_in[5];
    const float* Wa    = (const float*)d_in[6];
    const float* ba    = (const float*)d_in[7];

    float* out_v = (float*)d_out;                   // [B,T,D]
    float* out_e = out_v + (size_t)B_ * T_ * D_;    // [B,T,T]

    dim3 g1(T_/8, B_);
    prep_kernel<<<g1, 256>>>(input, demo, Wt, Wx, Wd, bh);

    dim3 g2(T_/8, T_/128, B_);
    score_kernel<<<g2, 128>>>(Wa, ba, out_e);

    dim3 g3(T_/8, B_);
    sv_kernel<<<g3, 256>>>(input, out_e, out_v);
}